// round 16
// baseline (speedup 1.0000x reference)
#include <cuda_runtime.h>
#include <cuda_fp16.h>
#include <math.h>

#define SEQ   2048
#define HEADS 24
#define CDIM  64
#define DDIM  256
#define SCALE 0.35355339059327373f   // 1/sqrt(8)

// ---- scratch (static device allocations; no cudaMalloc anywhere) ----
__device__ __half g_k[HEADS * SEQ * CDIM];     // [h][s][c] pre-scaled, fp16
__device__ __half g_q[HEADS * SEQ * CDIM];     // [h][s][c] fp16
__device__ float g_val[HEADS * SEQ * DDIM];    // [h][s][d] f32
__device__ __half g_valh[HEADS * DDIM * SEQ];  // [h][d][s] fp16 transposed
__device__ float g_part[HEADS * SEQ * DDIM];   // [h][s][d] per-head outputs

__device__ __forceinline__ float tf32r(float x) {
    unsigned u;
    asm("cvt.rna.tf32.f32 %0, %1;" : "=r"(u) : "f"(x));
    return __uint_as_float(u);
}

__device__ __forceinline__ unsigned f16x2_pack(float lo, float hi) {
    unsigned r;
    asm("cvt.rn.f16x2.f32 %0, %1, %2;" : "=r"(r) : "f"(hi), "f"(lo));
    return r;
}

__device__ __forceinline__ void mma_tf32(float c[4],
    unsigned a0, unsigned a1, unsigned a2, unsigned a3,
    unsigned b0, unsigned b1)
{
    asm volatile(
        "mma.sync.aligned.m16n8k8.row.col.f32.tf32.tf32.f32 "
        "{%0,%1,%2,%3}, {%4,%5,%6,%7}, {%8,%9}, {%0,%1,%2,%3};"
        : "+f"(c[0]), "+f"(c[1]), "+f"(c[2]), "+f"(c[3])
        : "r"(a0), "r"(a1), "r"(a2), "r"(a3), "r"(b0), "r"(b1));
}

__device__ __forceinline__ void mma_f16(float c[4],
    unsigned a0, unsigned a1, unsigned a2, unsigned a3,
    unsigned b0, unsigned b1)
{
    asm volatile(
        "mma.sync.aligned.m16n8k16.row.col.f32.f16.f16.f32 "
        "{%0,%1,%2,%3}, {%4,%5,%6,%7}, {%8,%9}, {%0,%1,%2,%3};"
        : "+f"(c[0]), "+f"(c[1]), "+f"(c[2]), "+f"(c[3])
        : "r"(a0), "r"(a1), "r"(a2), "r"(a3), "r"(b0), "r"(b1));
}

__device__ __forceinline__ unsigned smem_u32(const void* p) {
    unsigned a;
    asm("{ .reg .u64 t; cvta.to.shared.u64 t, %1; cvt.u32.u64 %0, t; }"
        : "=r"(a) : "l"(p));
    return a;
}

__device__ __forceinline__ void cp_async16(unsigned dst, const void* src) {
    asm volatile("cp.async.cg.shared.global [%0], [%1], 16;"
                 :: "r"(dst), "l"(src));
}
#define CP_ASYNC_COMMIT() asm volatile("cp.async.commit_group;" ::)
#define CP_ASYNC_WAIT0()  asm volatile("cp.async.wait_group 0;" ::: "memory")

// ============================================================================
// Tensor-core projection GEMM (unchanged; k/q stored fp16, val tf32)
// ============================================================================
#define GSTR 36

__device__ __forceinline__ void gscatter(int mode, int head_base,
                                         int s, int n, float v)
{
    if (mode == 0) {
        int h = head_base + (n >> 7);
        int c = n & 127;
        if (c < 64) g_k[(h * SEQ + s) * CDIM + c] = __float2half(v * SCALE);
        else        g_q[(h * SEQ + s) * CDIM + (c - 64)] = __float2half(v);
    } else {
        int h = n >> 8;
        int d = n & 255;
        g_val[(h * SEQ + s) * DDIM + d] = tf32r(v);
    }
}

__device__ __forceinline__ void mma_gemm(
    const float* __restrict__ A, const float* __restrict__ W,
    const float* __restrict__ bias, int K, int mode, int head_base)
{
    __shared__ float As[128 * GSTR];
    __shared__ float Bs[128 * GSTR];

    const int tid  = threadIdx.x;
    const int lane = tid & 31;
    const int wid  = tid >> 5;
    const int ty   = lane >> 2;
    const int tq   = lane & 3;
    const int wm   = wid & 3;
    const int wn   = wid >> 2;
    const int row0 = blockIdx.y * 128;
    const int col0 = blockIdx.x * 128;

    float acc[2][8][4];
#pragma unroll
    for (int mt = 0; mt < 2; mt++)
#pragma unroll
        for (int nt = 0; nt < 8; nt++)
#pragma unroll
            for (int e = 0; e < 4; e++) acc[mt][nt][e] = 0.0f;

    for (int k0 = 0; k0 < K; k0 += 32) {
        __syncthreads();
        const int rem = K - k0;
#pragma unroll
        for (int i = 0; i < 4; i++) {
            int flat = tid + i * 256;
            int r  = flat >> 3;
            int c4 = (flat & 7) * 4;
            float4 fa = make_float4(0.f, 0.f, 0.f, 0.f);
            float4 fb = make_float4(0.f, 0.f, 0.f, 0.f);
            const float* pa = A + (row0 + r) * K + k0 + c4;
            const float* pb = W + (col0 + r) * K + k0 + c4;
            if (c4 + 4 <= rem) {
                fa = *reinterpret_cast<const float4*>(pa);
                fb = *reinterpret_cast<const float4*>(pb);
            } else {
                if (c4 + 0 < rem) { fa.x = pa[0]; fb.x = pb[0]; }
                if (c4 + 1 < rem) { fa.y = pa[1]; fb.y = pb[1]; }
                if (c4 + 2 < rem) { fa.z = pa[2]; fb.z = pb[2]; }
                if (c4 + 3 < rem) { fa.w = pa[3]; fb.w = pb[3]; }
            }
            fa.x = tf32r(fa.x); fa.y = tf32r(fa.y);
            fa.z = tf32r(fa.z); fa.w = tf32r(fa.w);
            fb.x = tf32r(fb.x); fb.y = tf32r(fb.y);
            fb.z = tf32r(fb.z); fb.w = tf32r(fb.w);
            *reinterpret_cast<float4*>(As + r * GSTR + c4) = fa;
            *reinterpret_cast<float4*>(Bs + r * GSTR + c4) = fb;
        }
        __syncthreads();

#pragma unroll
        for (int kk = 0; kk < 4; kk++) {
            unsigned b0[8], b1[8];
#pragma unroll
            for (int nt = 0; nt < 8; nt++) {
                const float* pb = Bs + (wn * 64 + nt * 8 + ty) * GSTR + kk * 8 + tq;
                b0[nt] = __float_as_uint(pb[0]);
                b1[nt] = __float_as_uint(pb[4]);
            }
#pragma unroll
            for (int mt = 0; mt < 2; mt++) {
                const float* pa = As + (wm * 32 + mt * 16 + ty) * GSTR + kk * 8 + tq;
                unsigned a0 = __float_as_uint(pa[0]);
                unsigned a2 = __float_as_uint(pa[4]);
                unsigned a1 = __float_as_uint(pa[8 * GSTR]);
                unsigned a3 = __float_as_uint(pa[8 * GSTR + 4]);
#pragma unroll
                for (int nt = 0; nt < 8; nt++)
                    mma_tf32(acc[mt][nt], a0, a1, a2, a3, b0[nt], b1[nt]);
            }
        }
    }

#pragma unroll
    for (int nt = 0; nt < 8; nt++) {
        int n = col0 + wn * 64 + nt * 8 + 2 * tq;
        float2 bb = make_float2(0.f, 0.f);
        if (bias) bb = *reinterpret_cast<const float2*>(bias + n);
#pragma unroll
        for (int mt = 0; mt < 2; mt++) {
            int s0 = row0 + wm * 32 + mt * 16 + ty;
            gscatter(mode, head_base, s0,     n,     acc[mt][nt][0] + bb.x);
            gscatter(mode, head_base, s0,     n + 1, acc[mt][nt][1] + bb.y);
            gscatter(mode, head_base, s0 + 8, n,     acc[mt][nt][2] + bb.x);
            gscatter(mode, head_base, s0 + 8, n + 1, acc[mt][nt][3] + bb.y);
        }
    }
}

__global__ void __launch_bounds__(256, 2) kq_gemm(
    const float* __restrict__ nodes, const float* __restrict__ Wn, const float* __restrict__ bn,
    const float* __restrict__ aux,   const float* __restrict__ Wa, const float* __restrict__ ba,
    const float* __restrict__ rot,   const float* __restrict__ Wr)
{
    if (blockIdx.z == 0)       mma_gemm(nodes, Wn, bn,      256, 0, 0);
    else if (blockIdx.z == 1)  mma_gemm(aux,   Wa, ba,      64,  0, 8);
    else                       mma_gemm(rot,   Wr, nullptr, 4,   0, 16);
}

__global__ void __launch_bounds__(256, 2) val_gemm(
    const float* __restrict__ nodes, const float* __restrict__ Wv,
    const float* __restrict__ bv)
{
    mma_gemm(nodes, Wv, bv, 256, 1, 0);
}

// ============================================================================
// V transpose: g_val [h][s][d] f32 -> g_valh [h][d][s] fp16 (32x32 smem tile).
// ============================================================================
__global__ void __launch_bounds__(256) val_transpose()
{
    __shared__ float t[32][33];
    const int h  = blockIdx.z;
    const int d0 = blockIdx.x * 32;
    const int s0 = blockIdx.y * 32;
    const int tx = threadIdx.x & 31;
    const int ty = threadIdx.x >> 5;   // 0..7

    const float* in = g_val + h * SEQ * DDIM;
#pragma unroll
    for (int i = 0; i < 4; i++)
        t[ty + i * 8][tx] = in[(s0 + ty + i * 8) * DDIM + d0 + tx];
    __syncthreads();

    __half* outp = g_valh + h * DDIM * SEQ;
#pragma unroll
    for (int i = 0; i < 4; i++)
        outp[(d0 + ty + i * 8) * SEQ + s0 + tx] =
            __float2half(t[tx][ty + i * 8]);
}

// ============================================================================
// Flash attention, all-fp16 operands, fp32 accum, online-max softmax.
// Block: 128 i-rows x one head, 256 threads = 8 warps, j-tile 64.
// TWO syncs per tile, SINGLE-buffered Q/P/V -> smem 84 KB -> 2 CTAs/SM
// (16 warps): cross-CTA overlap fills barrier/softmax bubbles that pinned
// tensor util at 43% with 1 CTA/SM.
// Schedule (R13-proven hazard ordering):
//   commit Q(t) from regs; sync1 (Q visible; all warps past AV(t-1), so
//   V/P overwrites below are safe); cp.async V(t); score(t); softmax->P(t);
//   prefetch Q(t+1) regs; wait; sync2 (P,V,alpha visible); AV(t).
// All smem rows stride 36 u32 -> fragment LDS bank = 4*ty+tq: conflict-free.
// ============================================================================
#define SM_K   0                   // K: 128 x 36
#define SM_Q   (128 * 36)          // Q: 64 x 36
#define SM_P   (SM_Q + 64 * 36)    // P: 128 x 36
#define SM_V   (SM_P + 128 * 36)   // V: 256 x 36
#define SM_A   (SM_V + 256 * 36)   // alpha: 128
#define SM_L   (SM_A + 128)
#define ATTN_SMEM_BYTES ((SM_L + 128) * 4)

__global__ void __launch_bounds__(256, 2) attn_mma()
{
    extern __shared__ float sm[];
    const int tid  = threadIdx.x;
    const int lane = tid & 31;
    const int wid  = tid >> 5;    // 0..7
    const int ty   = lane >> 2;   // 0..7
    const int tq   = lane & 3;    // 0..3
    const int i0   = blockIdx.x * 128;
    const int h    = blockIdx.y;

    const __half* kb  = g_k + h * SEQ * CDIM;
    const __half* qb  = g_q + h * SEQ * CDIM;
    const __half* vbb = g_valh + h * DDIM * SEQ;

    // prologue: stage K tile (128 rows x 8 x 16B)
#pragma unroll
    for (int i = 0; i < 4; i++) {
        int flat = tid + i * 256;          // 0..1023
        int r  = flat >> 3;
        int ch = flat & 7;
        uint4 v = *reinterpret_cast<const uint4*>(kb + (i0 + r) * CDIM + ch * 8);
        *reinterpret_cast<uint4*>(sm + SM_K + r * 36 + ch * 4) = v;
    }

    // prefetch Q tile 0 into registers
    uint4 qreg[2];
#pragma unroll
    for (int i = 0; i < 2; i++) {
        int flat = tid + i * 256;          // 0..511
        int r  = flat >> 3;
        int ch = flat & 7;
        qreg[i] = *reinterpret_cast<const uint4*>(qb + r * CDIM + ch * 8);
    }

    float acc[8][4][4];
#pragma unroll
    for (int mt = 0; mt < 8; mt++)
#pragma unroll
        for (int nt = 0; nt < 4; nt++)
#pragma unroll
            for (int e = 0; e < 4; e++) acc[mt][nt][e] = 0.0f;

    float rowM[2] = {-1e30f, -1e30f};
    float rowL[2] = {0.0f, 0.0f};

    for (int t = 0; t < SEQ / 64; t++) {
        const int j0 = t * 64;

        // commit Q(t) (previous readers finished before last sync2)
#pragma unroll
        for (int i = 0; i < 2; i++) {
            int flat = tid + i * 256;
            int r  = flat >> 3;
            int ch = flat & 7;
            *reinterpret_cast<uint4*>(sm + SM_Q + r * 36 + ch * 4) = qreg[i];
        }
        __syncthreads();   // sync1: Q visible; all warps done with AV(t-1)

        // stage V(t) fp16 [d][j]: 2048 x 16B chunks (safe: post-sync1)
#pragma unroll
        for (int i = 0; i < 8; i++) {
            int flat = tid + i * 256;    // 0..2047
            int d  = flat >> 3;          // 0..255
            int ch = flat & 7;
            cp_async16(smem_u32(sm + SM_V + d * 36 + ch * 4),
                       vbb + d * SEQ + j0 + ch * 8);
        }
        CP_ASYNC_COMMIT();

        // ---------------- score fp16: warp w owns rows [16w,16w+16) -------
        float sc[8][4];
#pragma unroll
        for (int nt = 0; nt < 8; nt++)
#pragma unroll
            for (int e = 0; e < 4; e++) sc[nt][e] = 0.0f;

        const unsigned* Kp = reinterpret_cast<const unsigned*>(sm + SM_K);
        const unsigned* Qp = reinterpret_cast<const unsigned*>(sm + SM_Q);
#pragma unroll
        for (int kk = 0; kk < 4; kk++) {
            const unsigned* pa = Kp + (wid * 16 + ty) * 36 + kk * 8 + tq;
            unsigned a0 = pa[0];
            unsigned a2 = pa[4];
            unsigned a1 = pa[8 * 36];
            unsigned a3 = pa[8 * 36 + 4];
#pragma unroll
            for (int nt = 0; nt < 8; nt++) {
                const unsigned* qa = Qp + (nt * 8 + ty) * 36 + kk * 8 + tq;
                mma_f16(sc[nt], a0, a1, a2, a3, qa[0], qa[4]);
            }
        }

        // ---------------- online-max softmax: rows rA=16*wid+ty, rB=rA+8 --
        {
            float tmA = -1e30f, tmB = -1e30f;
#pragma unroll
            for (int nt = 0; nt < 8; nt++) {
                tmA = fmaxf(tmA, fmaxf(sc[nt][0], sc[nt][1]));
                tmB = fmaxf(tmB, fmaxf(sc[nt][2], sc[nt][3]));
            }
            tmA = fmaxf(tmA, __shfl_xor_sync(0xffffffffu, tmA, 1));
            tmA = fmaxf(tmA, __shfl_xor_sync(0xffffffffu, tmA, 2));
            tmB = fmaxf(tmB, __shfl_xor_sync(0xffffffffu, tmB, 1));
            tmB = fmaxf(tmB, __shfl_xor_sync(0xffffffffu, tmB, 2));

            float mnA = fmaxf(rowM[0], tmA);
            float mnB = fmaxf(rowM[1], tmB);
            float alA = __expf(rowM[0] - mnA);
            float alB = __expf(rowM[1] - mnB);

            float sumA = 0.0f, sumB = 0.0f;
            const int rA = wid * 16 + ty;
            unsigned* ps = reinterpret_cast<unsigned*>(sm + SM_P);
#pragma unroll
            for (int nt = 0; nt < 8; nt++) {
                float p0 = __expf(sc[nt][0] - mnA);
                float p1 = __expf(sc[nt][1] - mnA);
                float p2 = __expf(sc[nt][2] - mnB);
                float p3 = __expf(sc[nt][3] - mnB);
                sumA += p0 + p1;
                sumB += p2 + p3;
                ps[rA * 36 + nt * 4 + tq]       = f16x2_pack(p0, p1);
                ps[(rA + 8) * 36 + nt * 4 + tq] = f16x2_pack(p2, p3);
            }
            sumA += __shfl_xor_sync(0xffffffffu, sumA, 1);
            sumA += __shfl_xor_sync(0xffffffffu, sumA, 2);
            sumB += __shfl_xor_sync(0xffffffffu, sumB, 1);
            sumB += __shfl_xor_sync(0xffffffffu, sumB, 2);

            rowL[0] = rowL[0] * alA + sumA;
            rowL[1] = rowL[1] * alB + sumB;
            rowM[0] = mnA;
            rowM[1] = mnB;
            if (tq == 0) {
                sm[SM_A + rA]     = alA;
                sm[SM_A + rA + 8] = alB;
            }
        }

        // prefetch Q(t+1) into registers (overlaps the cp.async wait)
        if (j0 + 64 < SEQ) {
#pragma unroll
            for (int i = 0; i < 2; i++) {
                int flat = tid + i * 256;
                int r  = flat >> 3;
                int ch = flat & 7;
                qreg[i] = *reinterpret_cast<const uint4*>(
                    qb + (j0 + 64 + r) * CDIM + ch * 8);
            }
        }

        CP_ASYNC_WAIT0();
        __syncthreads();   // sync2: P, alpha, V visible

        // ---------------- AV fp16: warp owns d-slice [32*wid, 32*wid+32) --
        const float* al = sm + SM_A;
#pragma unroll
        for (int mt = 0; mt < 8; mt++) {
            float aA = al[mt * 16 + ty];
            float aB = al[mt * 16 + ty + 8];
#pragma unroll
            for (int nt = 0; nt < 4; nt++) {
                acc[mt][nt][0] *= aA; acc[mt][nt][1] *= aA;
                acc[mt][nt][2] *= aB; acc[mt][nt][3] *= aB;
            }
        }

        const unsigned* vt = reinterpret_cast<const unsigned*>(sm + SM_V);
        const unsigned* pt = reinterpret_cast<const unsigned*>(sm + SM_P);
#pragma unroll
        for (int kk = 0; kk < 4; kk++) {
            unsigned bc[4][2];
#pragma unroll
            for (int nt = 0; nt < 4; nt++) {
                const unsigned* p = vt + (wid * 32 + nt * 8 + ty) * 36 + kk * 8 + tq;
                bc[nt][0] = p[0];
                bc[nt][1] = p[4];
            }
#pragma unroll
            for (int mt = 0; mt < 8; mt++) {
                const unsigned* pa = pt + (mt * 16 + ty) * 36 + kk * 8 + tq;
                unsigned a0 = pa[0];
                unsigned a2 = pa[4];
                unsigned a1 = pa[8 * 36];
                unsigned a3 = pa[8 * 36 + 4];
#pragma unroll
                for (int nt = 0; nt < 4; nt++)
                    mma_f16(acc[mt][nt], a0, a1, a2, a3, bc[nt][0], bc[nt][1]);
            }
        }
        // no trailing sync: next tile's sync1 fences P/V/Q reuse
    }

    // publish L, then normalize and write per-head partials
    __syncthreads();
    if (tq == 0) {
        sm[SM_L + wid * 16 + ty]     = rowL[0];
        sm[SM_L + wid * 16 + ty + 8] = rowL[1];
    }
    __syncthreads();

    float* ob = g_part + (h * SEQ + i0) * DDIM + wid * 32;
#pragma unroll
    for (int mt = 0; mt < 8; mt++) {
        float iA = 1.0f / sm[SM_L + mt * 16 + ty];
        float iB = 1.0f / sm[SM_L + mt * 16 + ty + 8];
#pragma unroll
        for (int nt = 0; nt < 4; nt++) {
            float2 wa = make_float2(acc[mt][nt][0] * iA, acc[mt][nt][1] * iA);
            float2 wb = make_float2(acc[mt][nt][2] * iB, acc[mt][nt][3] * iB);
            *reinterpret_cast<float2*>(ob + (mt * 16 + ty) * DDIM + nt * 8 + 2 * tq) = wa;
            *reinterpret_cast<float2*>(ob + (mt * 16 + ty + 8) * DDIM + nt * 8 + 2 * tq) = wb;
        }
    }
}

// ============================================================================
// Sum over the 24 heads.
// ============================================================================
__global__ void __launch_bounds__(256) reduce_heads(float* __restrict__ out)
{
    int i = blockIdx.x * blockDim.x + threadIdx.x;
    float s = 0.0f;
#pragma unroll
    for (int h = 0; h < HEADS; h++)
        s += g_part[h * SEQ * DDIM + i];
    out[i] = s;
}

// ============================================================================
// launch
// ============================================================================
extern "C" void kernel_launch(void* const* d_in, const int* in_sizes, int n_in,
                              void* d_out, int out_size)
{
    (void)in_sizes; (void)n_in; (void)out_size;
    const float* nodes   = (const float*)d_in[0];
    const float* aux     = (const float*)d_in[1];
    const float* rot     = (const float*)d_in[2];
    const float* W_nodes = (const float*)d_in[3];
    const float* b_nodes = (const float*)d_in[4];
    const float* W_aux   = (const float*)d_in[5];
    const float* b_aux   = (const float*)d_in[6];
    const float* W_rot   = (const float*)d_in[7];
    const float* W_val   = (const float*)d_in[8];
    const float* b_val   = (const float*)d_in[9];
    float* out = (float*)d_out;

    cudaFuncSetAttribute(attn_mma,
                         cudaFuncAttributeMaxDynamicSharedMemorySize,
                         ATTN_SMEM_BYTES);

    // tensor-core projections (k/q fp16, val tf32)
    kq_gemm<<<dim3(1024 / 128, SEQ / 128, 3), 256>>>(
        nodes, W_nodes, b_nodes, aux, W_aux, b_aux, rot, W_rot);
    val_gemm<<<dim3(6144 / 128, SEQ / 128), 256>>>(nodes, W_val, b_val);

    // V transpose to fp16 [h][d][s]
    val_transpose<<<dim3(DDIM / 32, SEQ / 32, HEADS), 256>>>();

    // tensor-core flash attention per (128-row i-tile, head), 2 CTAs/SM
    attn_mma<<<dim3(SEQ / 128, HEADS), 256, ATTN_SMEM_BYTES>>>();

    // head sum
    reduce_heads<<<(SEQ * DDIM) / 256, 256>>>(out);
}

// round 17
// speedup vs baseline: 2.0163x; 2.0163x over previous
#include <cuda_runtime.h>
#include <cuda_fp16.h>
#include <math.h>

#define SEQ   2048
#define HEADS 24
#define CDIM  64
#define DDIM  256
#define SCALE 0.35355339059327373f   // 1/sqrt(8)

// ---- scratch (static device allocations; no cudaMalloc anywhere) ----
__device__ __half g_k[HEADS * SEQ * CDIM];     // [h][s][c] pre-scaled, fp16
__device__ __half g_q[HEADS * SEQ * CDIM];     // [h][s][c] fp16
__device__ float g_val[HEADS * SEQ * DDIM];    // [h][s][d] f32
__device__ __half g_valh[HEADS * DDIM * SEQ];  // [h][d][s] fp16 transposed
__device__ float g_part[HEADS * SEQ * DDIM];   // [h][s][d] per-head outputs

__device__ __forceinline__ float tf32r(float x) {
    unsigned u;
    asm("cvt.rna.tf32.f32 %0, %1;" : "=r"(u) : "f"(x));
    return __uint_as_float(u);
}

__device__ __forceinline__ unsigned f16x2_pack(float lo, float hi) {
    unsigned r;
    asm("cvt.rn.f16x2.f32 %0, %1, %2;" : "=r"(r) : "f"(hi), "f"(lo));
    return r;
}

__device__ __forceinline__ void mma_tf32(float c[4],
    unsigned a0, unsigned a1, unsigned a2, unsigned a3,
    unsigned b0, unsigned b1)
{
    asm volatile(
        "mma.sync.aligned.m16n8k8.row.col.f32.tf32.tf32.f32 "
        "{%0,%1,%2,%3}, {%4,%5,%6,%7}, {%8,%9}, {%0,%1,%2,%3};"
        : "+f"(c[0]), "+f"(c[1]), "+f"(c[2]), "+f"(c[3])
        : "r"(a0), "r"(a1), "r"(a2), "r"(a3), "r"(b0), "r"(b1));
}

__device__ __forceinline__ void mma_f16(float c[4],
    unsigned a0, unsigned a1, unsigned a2, unsigned a3,
    unsigned b0, unsigned b1)
{
    asm volatile(
        "mma.sync.aligned.m16n8k16.row.col.f32.f16.f16.f32 "
        "{%0,%1,%2,%3}, {%4,%5,%6,%7}, {%8,%9}, {%0,%1,%2,%3};"
        : "+f"(c[0]), "+f"(c[1]), "+f"(c[2]), "+f"(c[3])
        : "r"(a0), "r"(a1), "r"(a2), "r"(a3), "r"(b0), "r"(b1));
}

__device__ __forceinline__ unsigned smem_u32(const void* p) {
    unsigned a;
    asm("{ .reg .u64 t; cvta.to.shared.u64 t, %1; cvt.u32.u64 %0, t; }"
        : "=r"(a) : "l"(p));
    return a;
}

__device__ __forceinline__ void cp_async16(unsigned dst, const void* src) {
    asm volatile("cp.async.cg.shared.global [%0], [%1], 16;"
                 :: "r"(dst), "l"(src));
}
#define CP_ASYNC_COMMIT() asm volatile("cp.async.commit_group;" ::)
#define CP_ASYNC_WAIT0()  asm volatile("cp.async.wait_group 0;" ::: "memory")

// ============================================================================
// Tensor-core projection GEMM (unchanged; k/q stored fp16, val tf32)
// ============================================================================
#define GSTR 36

__device__ __forceinline__ void gscatter(int mode, int head_base,
                                         int s, int n, float v)
{
    if (mode == 0) {
        int h = head_base + (n >> 7);
        int c = n & 127;
        if (c < 64) g_k[(h * SEQ + s) * CDIM + c] = __float2half(v * SCALE);
        else        g_q[(h * SEQ + s) * CDIM + (c - 64)] = __float2half(v);
    } else {
        int h = n >> 8;
        int d = n & 255;
        g_val[(h * SEQ + s) * DDIM + d] = tf32r(v);
    }
}

__device__ __forceinline__ void mma_gemm(
    const float* __restrict__ A, const float* __restrict__ W,
    const float* __restrict__ bias, int K, int mode, int head_base)
{
    __shared__ float As[128 * GSTR];
    __shared__ float Bs[128 * GSTR];

    const int tid  = threadIdx.x;
    const int lane = tid & 31;
    const int wid  = tid >> 5;
    const int ty   = lane >> 2;
    const int tq   = lane & 3;
    const int wm   = wid & 3;
    const int wn   = wid >> 2;
    const int row0 = blockIdx.y * 128;
    const int col0 = blockIdx.x * 128;

    float acc[2][8][4];
#pragma unroll
    for (int mt = 0; mt < 2; mt++)
#pragma unroll
        for (int nt = 0; nt < 8; nt++)
#pragma unroll
            for (int e = 0; e < 4; e++) acc[mt][nt][e] = 0.0f;

    for (int k0 = 0; k0 < K; k0 += 32) {
        __syncthreads();
        const int rem = K - k0;
#pragma unroll
        for (int i = 0; i < 4; i++) {
            int flat = tid + i * 256;
            int r  = flat >> 3;
            int c4 = (flat & 7) * 4;
            float4 fa = make_float4(0.f, 0.f, 0.f, 0.f);
            float4 fb = make_float4(0.f, 0.f, 0.f, 0.f);
            const float* pa = A + (row0 + r) * K + k0 + c4;
            const float* pb = W + (col0 + r) * K + k0 + c4;
            if (c4 + 4 <= rem) {
                fa = *reinterpret_cast<const float4*>(pa);
                fb = *reinterpret_cast<const float4*>(pb);
            } else {
                if (c4 + 0 < rem) { fa.x = pa[0]; fb.x = pb[0]; }
                if (c4 + 1 < rem) { fa.y = pa[1]; fb.y = pb[1]; }
                if (c4 + 2 < rem) { fa.z = pa[2]; fb.z = pb[2]; }
                if (c4 + 3 < rem) { fa.w = pa[3]; fb.w = pb[3]; }
            }
            fa.x = tf32r(fa.x); fa.y = tf32r(fa.y);
            fa.z = tf32r(fa.z); fa.w = tf32r(fa.w);
            fb.x = tf32r(fb.x); fb.y = tf32r(fb.y);
            fb.z = tf32r(fb.z); fb.w = tf32r(fb.w);
            *reinterpret_cast<float4*>(As + r * GSTR + c4) = fa;
            *reinterpret_cast<float4*>(Bs + r * GSTR + c4) = fb;
        }
        __syncthreads();

#pragma unroll
        for (int kk = 0; kk < 4; kk++) {
            unsigned b0[8], b1[8];
#pragma unroll
            for (int nt = 0; nt < 8; nt++) {
                const float* pb = Bs + (wn * 64 + nt * 8 + ty) * GSTR + kk * 8 + tq;
                b0[nt] = __float_as_uint(pb[0]);
                b1[nt] = __float_as_uint(pb[4]);
            }
#pragma unroll
            for (int mt = 0; mt < 2; mt++) {
                const float* pa = As + (wm * 32 + mt * 16 + ty) * GSTR + kk * 8 + tq;
                unsigned a0 = __float_as_uint(pa[0]);
                unsigned a2 = __float_as_uint(pa[4]);
                unsigned a1 = __float_as_uint(pa[8 * GSTR]);
                unsigned a3 = __float_as_uint(pa[8 * GSTR + 4]);
#pragma unroll
                for (int nt = 0; nt < 8; nt++)
                    mma_tf32(acc[mt][nt], a0, a1, a2, a3, b0[nt], b1[nt]);
            }
        }
    }

#pragma unroll
    for (int nt = 0; nt < 8; nt++) {
        int n = col0 + wn * 64 + nt * 8 + 2 * tq;
        float2 bb = make_float2(0.f, 0.f);
        if (bias) bb = *reinterpret_cast<const float2*>(bias + n);
#pragma unroll
        for (int mt = 0; mt < 2; mt++) {
            int s0 = row0 + wm * 32 + mt * 16 + ty;
            gscatter(mode, head_base, s0,     n,     acc[mt][nt][0] + bb.x);
            gscatter(mode, head_base, s0,     n + 1, acc[mt][nt][1] + bb.y);
            gscatter(mode, head_base, s0 + 8, n,     acc[mt][nt][2] + bb.x);
            gscatter(mode, head_base, s0 + 8, n + 1, acc[mt][nt][3] + bb.y);
        }
    }
}

__global__ void __launch_bounds__(256, 2) kq_gemm(
    const float* __restrict__ nodes, const float* __restrict__ Wn, const float* __restrict__ bn,
    const float* __restrict__ aux,   const float* __restrict__ Wa, const float* __restrict__ ba,
    const float* __restrict__ rot,   const float* __restrict__ Wr)
{
    if (blockIdx.z == 0)       mma_gemm(nodes, Wn, bn,      256, 0, 0);
    else if (blockIdx.z == 1)  mma_gemm(aux,   Wa, ba,      64,  0, 8);
    else                       mma_gemm(rot,   Wr, nullptr, 4,   0, 16);
}

__global__ void __launch_bounds__(256, 2) val_gemm(
    const float* __restrict__ nodes, const float* __restrict__ Wv,
    const float* __restrict__ bv)
{
    mma_gemm(nodes, Wv, bv, 256, 1, 0);
}

// ============================================================================
// V transpose: g_val [h][s][d] f32 -> g_valh [h][d][s] fp16 (32x32 smem tile).
// ============================================================================
__global__ void __launch_bounds__(256) val_transpose()
{
    __shared__ float t[32][33];
    const int h  = blockIdx.z;
    const int d0 = blockIdx.x * 32;
    const int s0 = blockIdx.y * 32;
    const int tx = threadIdx.x & 31;
    const int ty = threadIdx.x >> 5;   // 0..7

    const float* in = g_val + h * SEQ * DDIM;
#pragma unroll
    for (int i = 0; i < 4; i++)
        t[ty + i * 8][tx] = in[(s0 + ty + i * 8) * DDIM + d0 + tx];
    __syncthreads();

    __half* outp = g_valh + h * DDIM * SEQ;
#pragma unroll
    for (int i = 0; i < 4; i++)
        outp[(d0 + ty + i * 8) * SEQ + s0 + tx] =
            __float2half(t[tx][ty + i * 8]);
}

// ============================================================================
// Flash attention, all-fp16 operands, fp32 accum, online-max softmax.
// Block: 128 i-rows x one head, 256 threads = 8 warps, j-tile 64, 1 CTA/SM.
// R14 schedule (single sync-pair equivalent: one barrier per phase boundary)
// plus two latency cuts:
//  - V DOUBLE-buffered with distance-2 cp.async: V(t+1) issued right after
//    sync2(t), so its latency overlaps AV(t) + score(t+1) + softmax(t+1).
//    Hazard: buf[(t+1)&1] last read by AV(t-1), finished before sync2(t).
//  - K fragments (loop-invariant) hoisted into 16 registers after a
//    prologue barrier: -16 LDS/warp/tile, shorter score dep chain.
// All smem rows stride 36 u32 -> fragment LDS bank = 4*ty+tq: conflict-free.
// ============================================================================
#define SM_K   0                   // K: 128 x 36
#define SM_Q   (128 * 36)          // Q: 64 x 36
#define SM_P   (SM_Q + 64 * 36)    // P: 128 x 36
#define SM_V   (SM_P + 128 * 36)   // V: 2 bufs x 256 x 36
#define SM_A   (SM_V + 2 * 256 * 36)
#define SM_L   (SM_A + 128)
#define ATTN_SMEM_BYTES ((SM_L + 128) * 4)

__global__ void __launch_bounds__(256) attn_mma()
{
    extern __shared__ float sm[];
    const int tid  = threadIdx.x;
    const int lane = tid & 31;
    const int wid  = tid >> 5;    // 0..7
    const int ty   = lane >> 2;   // 0..7
    const int tq   = lane & 3;    // 0..3
    const int i0   = blockIdx.x * 128;
    const int h    = blockIdx.y;

    const __half* kb  = g_k + h * SEQ * CDIM;
    const __half* qb  = g_q + h * SEQ * CDIM;
    const __half* vbb = g_valh + h * DDIM * SEQ;

    // prologue: stage K tile (128 rows x 8 x 16B)
#pragma unroll
    for (int i = 0; i < 4; i++) {
        int flat = tid + i * 256;          // 0..1023
        int r  = flat >> 3;
        int ch = flat & 7;
        uint4 v = *reinterpret_cast<const uint4*>(kb + (i0 + r) * CDIM + ch * 8);
        *reinterpret_cast<uint4*>(sm + SM_K + r * 36 + ch * 4) = v;
    }
    // prefetch Q tile 0 into registers
    uint4 qreg[2];
#pragma unroll
    for (int i = 0; i < 2; i++) {
        int flat = tid + i * 256;          // 0..511
        int r  = flat >> 3;
        int ch = flat & 7;
        qreg[i] = *reinterpret_cast<const uint4*>(qb + r * CDIM + ch * 8);
    }
    // issue V(0) into buffer 0 (distance-2 pipeline head)
#pragma unroll
    for (int i = 0; i < 8; i++) {
        int flat = tid + i * 256;
        int d  = flat >> 3;
        int ch = flat & 7;
        cp_async16(smem_u32(sm + SM_V + d * 36 + ch * 4),
                   vbb + d * SEQ + ch * 8);
    }
    CP_ASYNC_COMMIT();

    __syncthreads();   // K visible for fragment hoist

    // hoist K fragments (loop-invariant over j): 4 kk x 4 regs
    unsigned ka0[4], ka1[4], ka2[4], ka3[4];
    {
        const unsigned* Kp = reinterpret_cast<const unsigned*>(sm + SM_K);
#pragma unroll
        for (int kk = 0; kk < 4; kk++) {
            const unsigned* pa = Kp + (wid * 16 + ty) * 36 + kk * 8 + tq;
            ka0[kk] = pa[0];
            ka2[kk] = pa[4];
            ka1[kk] = pa[8 * 36];
            ka3[kk] = pa[8 * 36 + 4];
        }
    }

    float acc[8][4][4];
#pragma unroll
    for (int mt = 0; mt < 8; mt++)
#pragma unroll
        for (int nt = 0; nt < 4; nt++)
#pragma unroll
            for (int e = 0; e < 4; e++) acc[mt][nt][e] = 0.0f;

    float rowM[2] = {-1e30f, -1e30f};
    float rowL[2] = {0.0f, 0.0f};

    for (int t = 0; t < SEQ / 64; t++) {
        const int j0  = t * 64;
        const int par = t & 1;

        // commit Q(t) (previous readers finished before last sync2)
#pragma unroll
        for (int i = 0; i < 2; i++) {
            int flat = tid + i * 256;
            int r  = flat >> 3;
            int ch = flat & 7;
            *reinterpret_cast<uint4*>(sm + SM_Q + r * 36 + ch * 4) = qreg[i];
        }
        __syncthreads();   // sync1: Q visible; all warps done with AV(t-1)

        // ---------------- score fp16: warp w owns rows [16w,16w+16) -------
        float sc[8][4];
#pragma unroll
        for (int nt = 0; nt < 8; nt++)
#pragma unroll
            for (int e = 0; e < 4; e++) sc[nt][e] = 0.0f;

        const unsigned* Qp = reinterpret_cast<const unsigned*>(sm + SM_Q);
#pragma unroll
        for (int kk = 0; kk < 4; kk++) {
#pragma unroll
            for (int nt = 0; nt < 8; nt++) {
                const unsigned* qa = Qp + (nt * 8 + ty) * 36 + kk * 8 + tq;
                mma_f16(sc[nt], ka0[kk], ka1[kk], ka2[kk], ka3[kk], qa[0], qa[4]);
            }
        }

        // ---------------- online-max softmax: rows rA=16*wid+ty, rB=rA+8 --
        {
            float tmA = -1e30f, tmB = -1e30f;
#pragma unroll
            for (int nt = 0; nt < 8; nt++) {
                tmA = fmaxf(tmA, fmaxf(sc[nt][0], sc[nt][1]));
                tmB = fmaxf(tmB, fmaxf(sc[nt][2], sc[nt][3]));
            }
            tmA = fmaxf(tmA, __shfl_xor_sync(0xffffffffu, tmA, 1));
            tmA = fmaxf(tmA, __shfl_xor_sync(0xffffffffu, tmA, 2));
            tmB = fmaxf(tmB, __shfl_xor_sync(0xffffffffu, tmB, 1));
            tmB = fmaxf(tmB, __shfl_xor_sync(0xffffffffu, tmB, 2));

            float mnA = fmaxf(rowM[0], tmA);
            float mnB = fmaxf(rowM[1], tmB);
            float alA = __expf(rowM[0] - mnA);
            float alB = __expf(rowM[1] - mnB);

            float sumA = 0.0f, sumB = 0.0f;
            const int rA = wid * 16 + ty;
            unsigned* ps = reinterpret_cast<unsigned*>(sm + SM_P);
#pragma unroll
            for (int nt = 0; nt < 8; nt++) {
                float p0 = __expf(sc[nt][0] - mnA);
                float p1 = __expf(sc[nt][1] - mnA);
                float p2 = __expf(sc[nt][2] - mnB);
                float p3 = __expf(sc[nt][3] - mnB);
                sumA += p0 + p1;
                sumB += p2 + p3;
                ps[rA * 36 + nt * 4 + tq]       = f16x2_pack(p0, p1);
                ps[(rA + 8) * 36 + nt * 4 + tq] = f16x2_pack(p2, p3);
            }
            sumA += __shfl_xor_sync(0xffffffffu, sumA, 1);
            sumA += __shfl_xor_sync(0xffffffffu, sumA, 2);
            sumB += __shfl_xor_sync(0xffffffffu, sumB, 1);
            sumB += __shfl_xor_sync(0xffffffffu, sumB, 2);

            rowL[0] = rowL[0] * alA + sumA;
            rowL[1] = rowL[1] * alB + sumB;
            rowM[0] = mnA;
            rowM[1] = mnB;
            if (tq == 0) {
                sm[SM_A + rA]     = alA;
                sm[SM_A + rA + 8] = alB;
            }
        }

        // prefetch Q(t+1) into registers
        if (j0 + 64 < SEQ) {
#pragma unroll
            for (int i = 0; i < 2; i++) {
                int flat = tid + i * 256;
                int r  = flat >> 3;
                int ch = flat & 7;
                qreg[i] = *reinterpret_cast<const uint4*>(
                    qb + (j0 + 64 + r) * CDIM + ch * 8);
            }
        }

        CP_ASYNC_WAIT0();   // V(t) landed (issued one tile ago -> fully hidden)
        __syncthreads();    // sync2: P, alpha, V(t) visible

        // issue V(t+1) into the other buffer (its previous reader AV(t-1)
        // finished before sync2 above)
        if (j0 + 64 < SEQ) {
            float* vdst = sm + SM_V + (par ^ 1) * (256 * 36);
#pragma unroll
            for (int i = 0; i < 8; i++) {
                int flat = tid + i * 256;
                int d  = flat >> 3;
                int ch = flat & 7;
                cp_async16(smem_u32(vdst + d * 36 + ch * 4),
                           vbb + d * SEQ + j0 + 64 + ch * 8);
            }
            CP_ASYNC_COMMIT();
        }

        // ---------------- AV fp16: warp owns d-slice [32*wid, 32*wid+32) --
        const float* al = sm + SM_A;
#pragma unroll
        for (int mt = 0; mt < 8; mt++) {
            float aA = al[mt * 16 + ty];
            float aB = al[mt * 16 + ty + 8];
#pragma unroll
            for (int nt = 0; nt < 4; nt++) {
                acc[mt][nt][0] *= aA; acc[mt][nt][1] *= aA;
                acc[mt][nt][2] *= aB; acc[mt][nt][3] *= aB;
            }
        }

        const unsigned* vt = reinterpret_cast<const unsigned*>(
            sm + SM_V + par * (256 * 36));
        const unsigned* pt = reinterpret_cast<const unsigned*>(sm + SM_P);
#pragma unroll
        for (int kk = 0; kk < 4; kk++) {
            unsigned bc[4][2];
#pragma unroll
            for (int nt = 0; nt < 4; nt++) {
                const unsigned* p = vt + (wid * 32 + nt * 8 + ty) * 36 + kk * 8 + tq;
                bc[nt][0] = p[0];
                bc[nt][1] = p[4];
            }
#pragma unroll
            for (int mt = 0; mt < 8; mt++) {
                const unsigned* pa = pt + (mt * 16 + ty) * 36 + kk * 8 + tq;
                unsigned a0 = pa[0];
                unsigned a2 = pa[4];
                unsigned a1 = pa[8 * 36];
                unsigned a3 = pa[8 * 36 + 4];
#pragma unroll
                for (int nt = 0; nt < 4; nt++)
                    mma_f16(acc[mt][nt], a0, a1, a2, a3, bc[nt][0], bc[nt][1]);
            }
        }
        // no trailing sync: next tile's sync1 fences P/Q reuse; V is
        // parity-buffered with its writer ordered by this tile's sync2.
    }

    // publish L, then normalize and write per-head partials
    __syncthreads();
    if (tq == 0) {
        sm[SM_L + wid * 16 + ty]     = rowL[0];
        sm[SM_L + wid * 16 + ty + 8] = rowL[1];
    }
    __syncthreads();

    float* ob = g_part + (h * SEQ + i0) * DDIM + wid * 32;
#pragma unroll
    for (int mt = 0; mt < 8; mt++) {
        float iA = 1.0f / sm[SM_L + mt * 16 + ty];
        float iB = 1.0f / sm[SM_L + mt * 16 + ty + 8];
#pragma unroll
        for (int nt = 0; nt < 4; nt++) {
            float2 wa = make_float2(acc[mt][nt][0] * iA, acc[mt][nt][1] * iA);
            float2 wb = make_float2(acc[mt][nt][2] * iB, acc[mt][nt][3] * iB);
            *reinterpret_cast<float2*>(ob + (mt * 16 + ty) * DDIM + nt * 8 + 2 * tq) = wa;
            *reinterpret_cast<float2*>(ob + (mt * 16 + ty + 8) * DDIM + nt * 8 + 2 * tq) = wb;
        }
    }
}

// ============================================================================
// Sum over the 24 heads.
// ============================================================================
__global__ void __launch_bounds__(256) reduce_heads(float* __restrict__ out)
{
    int i = blockIdx.x * blockDim.x + threadIdx.x;
    float s = 0.0f;
#pragma unroll
    for (int h = 0; h < HEADS; h++)
        s += g_part[h * SEQ * DDIM + i];
    out[i] = s;
}

// ============================================================================
// launch
// ============================================================================
extern "C" void kernel_launch(void* const* d_in, const int* in_sizes, int n_in,
                              void* d_out, int out_size)
{
    (void)in_sizes; (void)n_in; (void)out_size;
    const float* nodes   = (const float*)d_in[0];
    const float* aux     = (const float*)d_in[1];
    const float* rot     = (const float*)d_in[2];
    const float* W_nodes = (const float*)d_in[3];
    const float* b_nodes = (const float*)d_in[4];
    const float* W_aux   = (const float*)d_in[5];
    const float* b_aux   = (const float*)d_in[6];
    const float* W_rot   = (const float*)d_in[7];
    const float* W_val   = (const float*)d_in[8];
    const float* b_val   = (const float*)d_in[9];
    float* out = (float*)d_out;

    cudaFuncSetAttribute(attn_mma,
                         cudaFuncAttributeMaxDynamicSharedMemorySize,
                         ATTN_SMEM_BYTES);

    // tensor-core projections (k/q fp16, val tf32)
    kq_gemm<<<dim3(1024 / 128, SEQ / 128, 3), 256>>>(
        nodes, W_nodes, b_nodes, aux, W_aux, b_aux, rot, W_rot);
    val_gemm<<<dim3(6144 / 128, SEQ / 128), 256>>>(nodes, W_val, b_val);

    // V transpose to fp16 [h][d][s]
    val_transpose<<<dim3(DDIM / 32, SEQ / 32, HEADS), 256>>>();

    // tensor-core flash attention per (128-row i-tile, head)
    attn_mma<<<dim3(SEQ / 128, HEADS), 256, ATTN_SMEM_BYTES>>>();

    // head sum
    reduce_heads<<<(SEQ * DDIM) / 256, 256>>>(out);
}